// round 9
// baseline (speedup 1.0000x reference)
#include <cuda_runtime.h>
#include <cuda_bf16.h>
#include <cstdint>

#define NUM_NODES 20000
#define SEQ_LEN 128
#define HIDDEN 32
#define N_TOTAL (NUM_NODES * SEQ_LEN)        // 2,560,000
#define N_EDGES 2000000

__device__ float g_agg2[(size_t)N_TOTAL * 2];
__device__ float g_deg[N_TOTAL];

// ---------------------------------------------------------------------------
// GCN kernels (edge_index arrives as int32)
// ---------------------------------------------------------------------------

__global__ void deg_kernel(const int* __restrict__ ei, float* __restrict__ deg) {
    int e = blockIdx.x * blockDim.x + threadIdx.x;
    if (e < N_EDGES) {
        int dst = ei[N_EDGES + e];
        atomicAdd(deg + dst, 1.0f);
    }
}

__global__ void dinv_kernel(float* __restrict__ deg) {
    int i = blockIdx.x * blockDim.x + threadIdx.x;
    if (i < N_TOTAL) {
        deg[i] = rsqrtf(deg[i] + 1.0f);
    }
}

__global__ void edge_scatter2(const int* __restrict__ ei,
                              const float* __restrict__ x,
                              const float* __restrict__ dinv,
                              float* __restrict__ agg2) {
    int e = blockIdx.x * blockDim.x + threadIdx.x;
    if (e >= N_EDGES) return;
    int src = ei[e];
    int dst = ei[N_EDGES + e];
    float norm = dinv[src] * dinv[dst];
    float2 xv = *(const float2*)(x + 2 * (size_t)src);
    float* p = agg2 + 2 * (size_t)dst;
    atomicAdd(p, xv.x * norm);
    atomicAdd(p + 1, xv.y * norm);
}

// ---------------------------------------------------------------------------
// LSTM v4: warp-uniform weights + 2 nodes per thread (weight LDS amortized
// over 64 nodes per warp) + MUFU.TANH nonlinearities.
// Block = 128 threads = 2 warp-pairs; pair p handles nodes [p*64, p*64+64),
// lane l of each pair-warp owns nodes l and l+32; warp's uhalf = 16 u-rows.
// ---------------------------------------------------------------------------

typedef unsigned long long ull;

__device__ __forceinline__ ull ffma2(ull a, ull b, ull c) {
    ull d;
    asm("fma.rn.f32x2 %0, %1, %2, %3;" : "=l"(d) : "l"(a), "l"(b), "l"(c));
    return d;
}
__device__ __forceinline__ ull pk(float lo, float hi) {
    ull r;
    asm("mov.b64 %0, {%1, %2};" : "=l"(r) : "f"(lo), "f"(hi));
    return r;
}
__device__ __forceinline__ float2 upk(ull v) {
    float2 r;
    asm("mov.b64 {%0, %1}, %2;" : "=f"(r.x), "=f"(r.y) : "l"(v));
    return r;
}
__device__ __forceinline__ float tanh_hw(float v) {
    float r;
    asm("tanh.approx.f32 %0, %1;" : "=f"(r) : "f"(v));
    return r;
}
__device__ __forceinline__ float sigmoid_hw(float v) {
    return fmaf(0.5f, tanh_hw(0.5f * v), 0.5f);
}

#define TPB_LSTM 128
#define NODES_PER_BLOCK 128
#define ST_PITCH 34          // even pitch -> 8B-aligned rows, conflict-free

// dynamic smem layout (floats)
#define SM_WI 0
#define SM_WH 4096
#define SM_BIAS 8192
#define SM_FCW 8320
#define SM_GW0 8352
#define SM_GW1 8384
#define SM_GB 8416
#define SM_HX 8448
#define SM_C (SM_HX + NODES_PER_BLOCK * ST_PITCH)
#define SM_FLOATS (SM_C + NODES_PER_BLOCK * ST_PITCH)
#define SM_BYTES (SM_FLOATS * 4)

__global__ void __launch_bounds__(TPB_LSTM)
lstm_kernel(const float* __restrict__ xg2,
            const float* __restrict__ agg2,
            const float* __restrict__ dinv,
            const float* __restrict__ gcnW, const float* __restrict__ gcnb,
            const float* __restrict__ w_ih, const float* __restrict__ w_hh,
            const float* __restrict__ b_ih, const float* __restrict__ b_hh,
            const float* __restrict__ fcW, const float* __restrict__ fcb,
            float* __restrict__ out) {
    extern __shared__ __align__(16) float sm[];
    float* s_wi = sm + SM_WI;
    float* s_wh = sm + SM_WH;
    float* s_bias = sm + SM_BIAS;
    float* s_fcw = sm + SM_FCW;
    float* s_gw0 = sm + SM_GW0;
    float* s_gw1 = sm + SM_GW1;
    float* s_gb = sm + SM_GB;
    float* s_hx = sm + SM_HX;
    float* s_c = sm + SM_C;

    int tid = threadIdx.x;
    for (int i = tid; i < 4096; i += TPB_LSTM) {
        s_wi[i] = w_ih[i];
        s_wh[i] = w_hh[i];
    }
    if (tid < 128) s_bias[tid] = b_ih[tid] + b_hh[tid];
    if (tid < 32) {
        s_fcw[tid] = fcW[tid];
        s_gw0[tid] = gcnW[tid];
        s_gw1[tid] = gcnW[32 + tid];
        s_gb[tid] = gcnb[tid];
    }
    for (int i = tid; i < NODES_PER_BLOCK * ST_PITCH; i += TPB_LSTM) {
        s_hx[i] = 0.0f;
        s_c[i] = 0.0f;
    }
    __syncthreads();

    int warp = tid >> 5;
    int lane = tid & 31;
    int pair = warp >> 1;
    int uhalf = warp & 1;          // warp-uniform
    int ubase = uhalf * 16;
    int nib0 = pair * 64 + lane;   // first node in block
    int nib1 = nib0 + 32;          // second node in block

    int na0 = blockIdx.x * NODES_PER_BLOCK + nib0;
    int na1 = blockIdx.x * NODES_PER_BLOCK + nib1;
    bool v0ok = na0 < NUM_NODES;
    bool v1ok = na1 < NUM_NODES;
    int n0 = v0ok ? na0 : NUM_NODES - 1;
    int n1 = v1ok ? na1 : NUM_NODES - 1;

    const float2* xp0 = (const float2*)(xg2 + (size_t)n0 * SEQ_LEN * 2);
    const float2* ap0 = (const float2*)(agg2 + (size_t)n0 * SEQ_LEN * 2);
    const float* dp0 = dinv + (size_t)n0 * SEQ_LEN;
    const float2* xp1 = (const float2*)(xg2 + (size_t)n1 * SEQ_LEN * 2);
    const float2* ap1 = (const float2*)(agg2 + (size_t)n1 * SEQ_LEN * 2);
    const float* dp1 = dinv + (size_t)n1 * SEQ_LEN;

    float* c0 = s_c + nib0 * ST_PITCH + ubase;
    float* c1 = s_c + nib1 * ST_PITCH + ubase;
    float* hx0 = s_hx + nib0 * ST_PITCH;
    float* hx1 = s_hx + nib1 * ST_PITCH;

    ull x2a[16], x2b[16], h2a[16], h2b[16];
#pragma unroll
    for (int j = 0; j < 16; j++) { h2a[j] = 0ull; h2b[j] = 0ull; }

    float2 nx0 = xp0[0], na0v = ap0[0];
    float2 nx1 = xp1[0], na1v = ap1[0];
    float nd0 = dp0[0], nd1 = dp1[0];

#pragma unroll 1
    for (int t = 0; t < SEQ_LEN; t++) {
        float2 xv0 = nx0, av0 = na0v, xv1 = nx1, av1 = na1v;
        float di0 = nd0, di1 = nd1;
        int tn = t + 1 < SEQ_LEN ? t + 1 : t;
        nx0 = xp0[tn]; na0v = ap0[tn]; nd0 = dp0[tn];
        nx1 = xp1[tn]; na1v = ap1[tn]; nd1 = dp1[tn];

        // fused GCN finalize for both nodes
        float d20 = di0 * di0, d21 = di1 * di1;
        float p0 = fmaf(xv0.x, d20, av0.x), p1 = fmaf(xv0.y, d20, av0.y);
        float q0 = fmaf(xv1.x, d21, av1.x), q1 = fmaf(xv1.y, d21, av1.y);
#pragma unroll
        for (int j = 0; j < 16; j++) {
            float ga = fmaxf(fmaf(p0, s_gw0[2 * j], fmaf(p1, s_gw1[2 * j], s_gb[2 * j])), 0.0f);
            float gb_ = fmaxf(fmaf(p0, s_gw0[2 * j + 1], fmaf(p1, s_gw1[2 * j + 1], s_gb[2 * j + 1])), 0.0f);
            x2a[j] = pk(ga, gb_);
            float gc = fmaxf(fmaf(q0, s_gw0[2 * j], fmaf(q1, s_gw1[2 * j], s_gb[2 * j])), 0.0f);
            float gd = fmaxf(fmaf(q0, s_gw0[2 * j + 1], fmaf(q1, s_gw1[2 * j + 1], s_gb[2 * j + 1])), 0.0f);
            x2b[j] = pk(gc, gd);
        }

#pragma unroll 2
        for (int uu = 0; uu < 16; uu++) {
            int u = ubase + uu;                    // warp-uniform
            const ulonglong2* pxi = (const ulonglong2*)(s_wi + u * 32);
            const ulonglong2* pxf = (const ulonglong2*)(s_wi + (u + 32) * 32);
            const ulonglong2* pxg = (const ulonglong2*)(s_wi + (u + 64) * 32);
            const ulonglong2* pxo = (const ulonglong2*)(s_wi + (u + 96) * 32);
            const ulonglong2* phi = (const ulonglong2*)(s_wh + u * 32);
            const ulonglong2* phf = (const ulonglong2*)(s_wh + (u + 32) * 32);
            const ulonglong2* phg = (const ulonglong2*)(s_wh + (u + 64) * 32);
            const ulonglong2* pho = (const ulonglong2*)(s_wh + (u + 96) * 32);
            ull ai0 = 0, af0 = 0, ag0 = 0, ao0 = 0;
            ull ai1 = 0, af1 = 0, ag1 = 0, ao1 = 0;
#pragma unroll
            for (int j = 0; j < 8; j++) {
                ulonglong2 w;
                w = pxi[j];
                ai0 = ffma2(w.x, x2a[2 * j], ai0); ai0 = ffma2(w.y, x2a[2 * j + 1], ai0);
                ai1 = ffma2(w.x, x2b[2 * j], ai1); ai1 = ffma2(w.y, x2b[2 * j + 1], ai1);
                w = pxf[j];
                af0 = ffma2(w.x, x2a[2 * j], af0); af0 = ffma2(w.y, x2a[2 * j + 1], af0);
                af1 = ffma2(w.x, x2b[2 * j], af1); af1 = ffma2(w.y, x2b[2 * j + 1], af1);
                w = pxg[j];
                ag0 = ffma2(w.x, x2a[2 * j], ag0); ag0 = ffma2(w.y, x2a[2 * j + 1], ag0);
                ag1 = ffma2(w.x, x2b[2 * j], ag1); ag1 = ffma2(w.y, x2b[2 * j + 1], ag1);
                w = pxo[j];
                ao0 = ffma2(w.x, x2a[2 * j], ao0); ao0 = ffma2(w.y, x2a[2 * j + 1], ao0);
                ao1 = ffma2(w.x, x2b[2 * j], ao1); ao1 = ffma2(w.y, x2b[2 * j + 1], ao1);
                w = phi[j];
                ai0 = ffma2(w.x, h2a[2 * j], ai0); ai0 = ffma2(w.y, h2a[2 * j + 1], ai0);
                ai1 = ffma2(w.x, h2b[2 * j], ai1); ai1 = ffma2(w.y, h2b[2 * j + 1], ai1);
                w = phf[j];
                af0 = ffma2(w.x, h2a[2 * j], af0); af0 = ffma2(w.y, h2a[2 * j + 1], af0);
                af1 = ffma2(w.x, h2b[2 * j], af1); af1 = ffma2(w.y, h2b[2 * j + 1], af1);
                w = phg[j];
                ag0 = ffma2(w.x, h2a[2 * j], ag0); ag0 = ffma2(w.y, h2a[2 * j + 1], ag0);
                ag1 = ffma2(w.x, h2b[2 * j], ag1); ag1 = ffma2(w.y, h2b[2 * j + 1], ag1);
                w = pho[j];
                ao0 = ffma2(w.x, h2a[2 * j], ao0); ao0 = ffma2(w.y, h2a[2 * j + 1], ao0);
                ao1 = ffma2(w.x, h2b[2 * j], ao1); ao1 = ffma2(w.y, h2b[2 * j + 1], ao1);
            }
            {
                float2 vi = upk(ai0), vf = upk(af0), vg = upk(ag0), vo = upk(ao0);
                float gi = sigmoid_hw(vi.x + vi.y + s_bias[u]);
                float gf = sigmoid_hw(vf.x + vf.y + s_bias[32 + u]);
                float gg = tanh_hw(vg.x + vg.y + s_bias[64 + u]);
                float go = sigmoid_hw(vo.x + vo.y + s_bias[96 + u]);
                float c = fmaf(gf, c0[uu], gi * gg);
                c0[uu] = c;
                hx0[ubase + uu] = go * tanh_hw(c);
            }
            {
                float2 vi = upk(ai1), vf = upk(af1), vg = upk(ag1), vo = upk(ao1);
                float gi = sigmoid_hw(vi.x + vi.y + s_bias[u]);
                float gf = sigmoid_hw(vf.x + vf.y + s_bias[32 + u]);
                float gg = tanh_hw(vg.x + vg.y + s_bias[64 + u]);
                float go = sigmoid_hw(vo.x + vo.y + s_bias[96 + u]);
                float c = fmaf(gf, c1[uu], gi * gg);
                c1[uu] = c;
                hx1[ubase + uu] = go * tanh_hw(c);
            }
        }

        __syncthreads();
#pragma unroll
        for (int j = 0; j < 16; j++) {
            h2a[j] = *(const ull*)(hx0 + 2 * j);
            h2b[j] = *(const ull*)(hx1 + 2 * j);
        }
        __syncthreads();
    }

    if (uhalf == 0) {
        float acc0 = fcb[0], acc1 = fcb[0];
#pragma unroll
        for (int j = 0; j < 16; j++) {
            float2 ha = upk(h2a[j]);
            float2 hb = upk(h2b[j]);
            acc0 = fmaf(ha.x, s_fcw[2 * j], acc0);
            acc0 = fmaf(ha.y, s_fcw[2 * j + 1], acc0);
            acc1 = fmaf(hb.x, s_fcw[2 * j], acc1);
            acc1 = fmaf(hb.y, s_fcw[2 * j + 1], acc1);
        }
        if (v0ok) out[na0] = acc0;
        if (v1ok) out[na1] = acc1;
    }
}

// ---------------------------------------------------------------------------

extern "C" void kernel_launch(void* const* d_in, const int* in_sizes, int n_in,
                              void* d_out, int out_size) {
    const float* x = (const float*)d_in[0];
    const int* ei = (const int*)d_in[1];
    const float* gcnW = (const float*)d_in[2];
    const float* gcnb = (const float*)d_in[3];
    const float* w_ih = (const float*)d_in[4];
    const float* w_hh = (const float*)d_in[5];
    const float* b_ih = (const float*)d_in[6];
    const float* b_hh = (const float*)d_in[7];
    const float* fcW = (const float*)d_in[8];
    const float* fcb = (const float*)d_in[9];
    float* out = (float*)d_out;

    void* aggp = nullptr;
    void* degp = nullptr;
    cudaGetSymbolAddress(&aggp, g_agg2);
    cudaGetSymbolAddress(&degp, g_deg);

    cudaMemsetAsync(aggp, 0, sizeof(float) * (size_t)N_TOTAL * 2);
    cudaMemsetAsync(degp, 0, sizeof(float) * (size_t)N_TOTAL);

    deg_kernel<<<(N_EDGES + 255) / 256, 256>>>(ei, (float*)degp);
    dinv_kernel<<<(N_TOTAL + 255) / 256, 256>>>((float*)degp);
    edge_scatter2<<<(N_EDGES + 255) / 256, 256>>>(ei, x, (const float*)degp, (float*)aggp);

    cudaFuncSetAttribute(lstm_kernel, cudaFuncAttributeMaxDynamicSharedMemorySize, SM_BYTES);
    int lstm_blocks = (NUM_NODES + NODES_PER_BLOCK - 1) / NODES_PER_BLOCK;  // 157
    lstm_kernel<<<lstm_blocks, TPB_LSTM, SM_BYTES>>>(
        x, (const float*)aggp, (const float*)degp, gcnW, gcnb,
        w_ih, w_hh, b_ih, b_hh, fcW, fcb, out);
}

// round 10
// speedup vs baseline: 1.7453x; 1.7453x over previous
#include <cuda_runtime.h>
#include <cuda_bf16.h>
#include <cstdint>

#define NUM_NODES 20000
#define SEQ_LEN 128
#define HIDDEN 32
#define N_TOTAL (NUM_NODES * SEQ_LEN)        // 2,560,000
#define N_EDGES 2000000

__device__ float g_agg2[(size_t)N_TOTAL * 2];
__device__ float g_deg[N_TOTAL];

// ---------------------------------------------------------------------------
// GCN kernels (edge_index arrives as int32)
// ---------------------------------------------------------------------------

__global__ void deg_kernel(const int* __restrict__ ei, float* __restrict__ deg) {
    int e = blockIdx.x * blockDim.x + threadIdx.x;
    if (e < N_EDGES) {
        int dst = ei[N_EDGES + e];
        atomicAdd(deg + dst, 1.0f);
    }
}

__global__ void dinv_kernel(float* __restrict__ deg) {
    int i = blockIdx.x * blockDim.x + threadIdx.x;
    if (i < N_TOTAL) {
        deg[i] = rsqrtf(deg[i] + 1.0f);
    }
}

__global__ void edge_scatter2(const int* __restrict__ ei,
                              const float* __restrict__ x,
                              const float* __restrict__ dinv,
                              float* __restrict__ agg2) {
    int e = blockIdx.x * blockDim.x + threadIdx.x;
    if (e >= N_EDGES) return;
    int src = ei[e];
    int dst = ei[N_EDGES + e];
    float norm = dinv[src] * dinv[dst];
    float2 xv = *(const float2*)(x + 2 * (size_t)src);
    float* p = agg2 + 2 * (size_t)dst;
    atomicAdd(p, xv.x * norm);
    atomicAdd(p + 1, xv.y * norm);
}

// ---------------------------------------------------------------------------
// LSTM v5: 4-way u-split x 2 nodes/thread.
// Block = 128 threads = 4 warps = one quad handling 64 nodes.
// Warp w computes u-rows [8w, 8w+8) for all 64 nodes (lane l owns nodes l and
// l+32). Weight LDS.128 broadcasts serve 64 nodes each; c lives in registers;
// h exchanged through padded SMEM with 2 barriers/step. MUFU.TANH gates.
// ---------------------------------------------------------------------------

typedef unsigned long long ull;

__device__ __forceinline__ ull ffma2(ull a, ull b, ull c) {
    ull d;
    asm("fma.rn.f32x2 %0, %1, %2, %3;" : "=l"(d) : "l"(a), "l"(b), "l"(c));
    return d;
}
__device__ __forceinline__ ull pk(float lo, float hi) {
    ull r;
    asm("mov.b64 %0, {%1, %2};" : "=l"(r) : "f"(lo), "f"(hi));
    return r;
}
__device__ __forceinline__ float2 upk(ull v) {
    float2 r;
    asm("mov.b64 {%0, %1}, %2;" : "=f"(r.x), "=f"(r.y) : "l"(v));
    return r;
}
__device__ __forceinline__ float tanh_hw(float v) {
    float r;
    asm("tanh.approx.f32 %0, %1;" : "=f"(r) : "f"(v));
    return r;
}
__device__ __forceinline__ float sigmoid_hw(float v) {
    return fmaf(0.5f, tanh_hw(0.5f * v), 0.5f);
}

#define TPB_LSTM 128
#define NODES_PER_BLOCK 64
#define ST_PITCH 34          // even pitch -> 8B-aligned rows, conflict-free

__global__ void __launch_bounds__(TPB_LSTM)
lstm_kernel(const float* __restrict__ xg2,
            const float* __restrict__ agg2,
            const float* __restrict__ dinv,
            const float* __restrict__ gcnW, const float* __restrict__ gcnb,
            const float* __restrict__ w_ih, const float* __restrict__ w_hh,
            const float* __restrict__ b_ih, const float* __restrict__ b_hh,
            const float* __restrict__ fcW, const float* __restrict__ fcb,
            float* __restrict__ out) {
    __shared__ __align__(16) float s_wi[4096];
    __shared__ __align__(16) float s_wh[4096];
    __shared__ float s_bias[128];
    __shared__ float s_fcw[32];
    __shared__ float s_gw0[32];
    __shared__ float s_gw1[32];
    __shared__ float s_gb[32];
    __shared__ __align__(16) float s_hx[NODES_PER_BLOCK * ST_PITCH];

    int tid = threadIdx.x;
    for (int i = tid; i < 4096; i += TPB_LSTM) {
        s_wi[i] = w_ih[i];
        s_wh[i] = w_hh[i];
    }
    if (tid < 128) s_bias[tid] = b_ih[tid] + b_hh[tid];
    if (tid < 32) {
        s_fcw[tid] = fcW[tid];
        s_gw0[tid] = gcnW[tid];
        s_gw1[tid] = gcnW[32 + tid];
        s_gb[tid] = gcnb[tid];
    }
    for (int i = tid; i < NODES_PER_BLOCK * ST_PITCH; i += TPB_LSTM) s_hx[i] = 0.0f;
    __syncthreads();

    int warp = tid >> 5;           // 0..3 = u-quarter (warp-uniform)
    int lane = tid & 31;
    int ubase = warp * 8;
    int nib0 = lane;               // node 0 in block
    int nib1 = lane + 32;          // node 1 in block

    int na0 = blockIdx.x * NODES_PER_BLOCK + nib0;
    int na1 = blockIdx.x * NODES_PER_BLOCK + nib1;
    bool v0ok = na0 < NUM_NODES;
    bool v1ok = na1 < NUM_NODES;
    int n0 = v0ok ? na0 : NUM_NODES - 1;
    int n1 = v1ok ? na1 : NUM_NODES - 1;

    const float2* xp0 = (const float2*)(xg2 + (size_t)n0 * SEQ_LEN * 2);
    const float2* ap0 = (const float2*)(agg2 + (size_t)n0 * SEQ_LEN * 2);
    const float* dp0 = dinv + (size_t)n0 * SEQ_LEN;
    const float2* xp1 = (const float2*)(xg2 + (size_t)n1 * SEQ_LEN * 2);
    const float2* ap1 = (const float2*)(agg2 + (size_t)n1 * SEQ_LEN * 2);
    const float* dp1 = dinv + (size_t)n1 * SEQ_LEN;

    float* hx0 = s_hx + nib0 * ST_PITCH;
    float* hx1 = s_hx + nib1 * ST_PITCH;

    ull x2a[16], x2b[16], h2a[16], h2b[16];
    float c0r[8], c1r[8];
#pragma unroll
    for (int j = 0; j < 16; j++) { h2a[j] = 0ull; h2b[j] = 0ull; }
#pragma unroll
    for (int j = 0; j < 8; j++) { c0r[j] = 0.0f; c1r[j] = 0.0f; }

    float2 nx0 = xp0[0], nav0 = ap0[0];
    float2 nx1 = xp1[0], nav1 = ap1[0];
    float nd0 = dp0[0], nd1 = dp1[0];

#pragma unroll 1
    for (int t = 0; t < SEQ_LEN; t++) {
        float2 xv0 = nx0, av0 = nav0, xv1 = nx1, av1 = nav1;
        float di0 = nd0, di1 = nd1;
        int tn = t + 1 < SEQ_LEN ? t + 1 : t;
        nx0 = xp0[tn]; nav0 = ap0[tn]; nd0 = dp0[tn];
        nx1 = xp1[tn]; nav1 = ap1[tn]; nd1 = dp1[tn];

        // fused GCN finalize for both nodes
        float d20 = di0 * di0, d21 = di1 * di1;
        float p0 = fmaf(xv0.x, d20, av0.x), p1 = fmaf(xv0.y, d20, av0.y);
        float q0 = fmaf(xv1.x, d21, av1.x), q1 = fmaf(xv1.y, d21, av1.y);
#pragma unroll
        for (int j = 0; j < 16; j++) {
            float ga = fmaxf(fmaf(p0, s_gw0[2 * j], fmaf(p1, s_gw1[2 * j], s_gb[2 * j])), 0.0f);
            float gb_ = fmaxf(fmaf(p0, s_gw0[2 * j + 1], fmaf(p1, s_gw1[2 * j + 1], s_gb[2 * j + 1])), 0.0f);
            x2a[j] = pk(ga, gb_);
            float gc = fmaxf(fmaf(q0, s_gw0[2 * j], fmaf(q1, s_gw1[2 * j], s_gb[2 * j])), 0.0f);
            float gd = fmaxf(fmaf(q0, s_gw0[2 * j + 1], fmaf(q1, s_gw1[2 * j + 1], s_gb[2 * j + 1])), 0.0f);
            x2b[j] = pk(gc, gd);
        }

#pragma unroll
        for (int uu = 0; uu < 8; uu++) {
            int u = ubase + uu;                    // warp-uniform
            const ulonglong2* pxi = (const ulonglong2*)(s_wi + u * 32);
            const ulonglong2* pxf = (const ulonglong2*)(s_wi + (u + 32) * 32);
            const ulonglong2* pxg = (const ulonglong2*)(s_wi + (u + 64) * 32);
            const ulonglong2* pxo = (const ulonglong2*)(s_wi + (u + 96) * 32);
            const ulonglong2* phi = (const ulonglong2*)(s_wh + u * 32);
            const ulonglong2* phf = (const ulonglong2*)(s_wh + (u + 32) * 32);
            const ulonglong2* phg = (const ulonglong2*)(s_wh + (u + 64) * 32);
            const ulonglong2* pho = (const ulonglong2*)(s_wh + (u + 96) * 32);
            ull ai0 = 0, af0 = 0, ag0 = 0, ao0 = 0;
            ull ai1 = 0, af1 = 0, ag1 = 0, ao1 = 0;
#pragma unroll
            for (int j = 0; j < 8; j++) {
                ulonglong2 w;
                w = pxi[j];
                ai0 = ffma2(w.x, x2a[2 * j], ai0); ai0 = ffma2(w.y, x2a[2 * j + 1], ai0);
                ai1 = ffma2(w.x, x2b[2 * j], ai1); ai1 = ffma2(w.y, x2b[2 * j + 1], ai1);
                w = pxf[j];
                af0 = ffma2(w.x, x2a[2 * j], af0); af0 = ffma2(w.y, x2a[2 * j + 1], af0);
                af1 = ffma2(w.x, x2b[2 * j], af1); af1 = ffma2(w.y, x2b[2 * j + 1], af1);
                w = pxg[j];
                ag0 = ffma2(w.x, x2a[2 * j], ag0); ag0 = ffma2(w.y, x2a[2 * j + 1], ag0);
                ag1 = ffma2(w.x, x2b[2 * j], ag1); ag1 = ffma2(w.y, x2b[2 * j + 1], ag1);
                w = pxo[j];
                ao0 = ffma2(w.x, x2a[2 * j], ao0); ao0 = ffma2(w.y, x2a[2 * j + 1], ao0);
                ao1 = ffma2(w.x, x2b[2 * j], ao1); ao1 = ffma2(w.y, x2b[2 * j + 1], ao1);
                w = phi[j];
                ai0 = ffma2(w.x, h2a[2 * j], ai0); ai0 = ffma2(w.y, h2a[2 * j + 1], ai0);
                ai1 = ffma2(w.x, h2b[2 * j], ai1); ai1 = ffma2(w.y, h2b[2 * j + 1], ai1);
                w = phf[j];
                af0 = ffma2(w.x, h2a[2 * j], af0); af0 = ffma2(w.y, h2a[2 * j + 1], af0);
                af1 = ffma2(w.x, h2b[2 * j], af1); af1 = ffma2(w.y, h2b[2 * j + 1], af1);
                w = phg[j];
                ag0 = ffma2(w.x, h2a[2 * j], ag0); ag0 = ffma2(w.y, h2a[2 * j + 1], ag0);
                ag1 = ffma2(w.x, h2b[2 * j], ag1); ag1 = ffma2(w.y, h2b[2 * j + 1], ag1);
                w = pho[j];
                ao0 = ffma2(w.x, h2a[2 * j], ao0); ao0 = ffma2(w.y, h2a[2 * j + 1], ao0);
                ao1 = ffma2(w.x, h2b[2 * j], ao1); ao1 = ffma2(w.y, h2b[2 * j + 1], ao1);
            }
            {
                float2 vi = upk(ai0), vf = upk(af0), vg = upk(ag0), vo = upk(ao0);
                float gi = sigmoid_hw(vi.x + vi.y + s_bias[u]);
                float gf = sigmoid_hw(vf.x + vf.y + s_bias[32 + u]);
                float gg = tanh_hw(vg.x + vg.y + s_bias[64 + u]);
                float go = sigmoid_hw(vo.x + vo.y + s_bias[96 + u]);
                float c = fmaf(gf, c0r[uu], gi * gg);
                c0r[uu] = c;
                hx0[u] = go * tanh_hw(c);
            }
            {
                float2 vi = upk(ai1), vf = upk(af1), vg = upk(ag1), vo = upk(ao1);
                float gi = sigmoid_hw(vi.x + vi.y + s_bias[u]);
                float gf = sigmoid_hw(vf.x + vf.y + s_bias[32 + u]);
                float gg = tanh_hw(vg.x + vg.y + s_bias[64 + u]);
                float go = sigmoid_hw(vo.x + vo.y + s_bias[96 + u]);
                float c = fmaf(gf, c1r[uu], gi * gg);
                c1r[uu] = c;
                hx1[u] = go * tanh_hw(c);
            }
        }

        __syncthreads();   // all 4 warps published their u-quarters
#pragma unroll
        for (int j = 0; j < 16; j++) {
            h2a[j] = *(const ull*)(hx0 + 2 * j);
            h2b[j] = *(const ull*)(hx1 + 2 * j);
        }
        __syncthreads();   // reads done before next-step writes
    }

    if (warp == 0) {
        float acc0 = fcb[0], acc1 = fcb[0];
#pragma unroll
        for (int j = 0; j < 16; j++) {
            float2 ha = upk(h2a[j]);
            float2 hb = upk(h2b[j]);
            acc0 = fmaf(ha.x, s_fcw[2 * j], acc0);
            acc0 = fmaf(ha.y, s_fcw[2 * j + 1], acc0);
            acc1 = fmaf(hb.x, s_fcw[2 * j], acc1);
            acc1 = fmaf(hb.y, s_fcw[2 * j + 1], acc1);
        }
        if (v0ok) out[na0] = acc0;
        if (v1ok) out[na1] = acc1;
    }
}

// ---------------------------------------------------------------------------

extern "C" void kernel_launch(void* const* d_in, const int* in_sizes, int n_in,
                              void* d_out, int out_size) {
    const float* x = (const float*)d_in[0];
    const int* ei = (const int*)d_in[1];
    const float* gcnW = (const float*)d_in[2];
    const float* gcnb = (const float*)d_in[3];
    const float* w_ih = (const float*)d_in[4];
    const float* w_hh = (const float*)d_in[5];
    const float* b_ih = (const float*)d_in[6];
    const float* b_hh = (const float*)d_in[7];
    const float* fcW = (const float*)d_in[8];
    const float* fcb = (const float*)d_in[9];
    float* out = (float*)d_out;

    void* aggp = nullptr;
    void* degp = nullptr;
    cudaGetSymbolAddress(&aggp, g_agg2);
    cudaGetSymbolAddress(&degp, g_deg);

    cudaMemsetAsync(aggp, 0, sizeof(float) * (size_t)N_TOTAL * 2);
    cudaMemsetAsync(degp, 0, sizeof(float) * (size_t)N_TOTAL);

    deg_kernel<<<(N_EDGES + 255) / 256, 256>>>(ei, (float*)degp);
    dinv_kernel<<<(N_TOTAL + 255) / 256, 256>>>((float*)degp);
    edge_scatter2<<<(N_EDGES + 255) / 256, 256>>>(ei, x, (const float*)degp, (float*)aggp);

    int lstm_blocks = (NUM_NODES + NODES_PER_BLOCK - 1) / NODES_PER_BLOCK;  // 313
    lstm_kernel<<<lstm_blocks, TPB_LSTM>>>(
        x, (const float*)aggp, (const float*)degp, gcnW, gcnb,
        w_ih, w_hh, b_ih, b_hh, fcW, fcb, out);
}